// round 5
// baseline (speedup 1.0000x reference)
#include <cuda_runtime.h>
#include <math.h>
#include <stdint.h>

#define DIM   512
#define HEADS 8
#define DQ    64
#define SEQ   4096
#define BATCH 2
#define NTOK  (BATCH * SEQ)   // 8192

// Scratch (allocation-free rule: __device__ globals)
__device__ float g_q [NTOK * DIM];
__device__ float g_k [NTOK * DIM];
__device__ float g_vt[NTOK * DIM];   // V stored transposed: [b*512 + m][4096]
__device__ float g_ao[NTOK * DIM];

// ---------------------------------------------------------------------------
// helpers
// ---------------------------------------------------------------------------
__device__ __forceinline__ uint32_t f2tf32(float f) {
    uint32_t u; asm("cvt.rna.tf32.f32 %0, %1;" : "=r"(u) : "f"(f)); return u;
}
__device__ __forceinline__ float f2tf32f(float f) { return __uint_as_float(f2tf32(f)); }

__device__ __forceinline__ void sts_tf4(float* d, float4 v) {
    d[0] = f2tf32f(v.x); d[1] = f2tf32f(v.y);
    d[2] = f2tf32f(v.z); d[3] = f2tf32f(v.w);
}

__device__ __forceinline__ void ldsm_x4(uint32_t r[4], const float* p) {
    uint32_t a = (uint32_t)__cvta_generic_to_shared(p);
    asm volatile("ldmatrix.sync.aligned.m8n8.x4.shared.b16 {%0,%1,%2,%3}, [%4];"
                 : "=r"(r[0]), "=r"(r[1]), "=r"(r[2]), "=r"(r[3])
                 : "r"(a) : "memory");
}

// round raw fp32 fragment bits to tf32 in-register (b32 regs are type-compatible)
__device__ __forceinline__ void cvt4(uint32_t r[4]) {
    #pragma unroll
    for (int i = 0; i < 4; i++)
        asm("cvt.rna.tf32.f32 %0, %0;" : "+r"(r[i]));
}

__device__ __forceinline__ void mma_tf32(float c[4], const uint32_t a[4],
                                         uint32_t b0, uint32_t b1) {
    asm volatile("mma.sync.aligned.m16n8k8.row.col.f32.tf32.tf32.f32 "
                 "{%0,%1,%2,%3}, {%4,%5,%6,%7}, {%8,%9}, {%0,%1,%2,%3};"
                 : "+f"(c[0]), "+f"(c[1]), "+f"(c[2]), "+f"(c[3])
                 : "r"(a[0]), "r"(a[1]), "r"(a[2]), "r"(a[3]), "r"(b0), "r"(b1));
}

__device__ __forceinline__ void cp16(float* smem_dst, const float* gsrc) {
    uint32_t a = (uint32_t)__cvta_generic_to_shared(smem_dst);
    asm volatile("cp.async.cg.shared.global [%0], [%1], 16;" :: "r"(a), "l"(gsrc));
}
#define CP_COMMIT() asm volatile("cp.async.commit_group;")
#define CP_WAIT1()  asm volatile("cp.async.wait_group 1;")

// ---------------------------------------------------------------------------
// Tensor-core GEMM: C[n,m] = sum_k X[n,k]*W[m,k] + bias[m]   (K = 512)
// CTA: 128 tokens x 64 cols.  8 warps.  cp.async double-buffered k-steps of 32.
// transposed!=0: write C^T into [(b*512 + m)][4096] layout (for V).
// ---------------------------------------------------------------------------
#define GP 36   // shared pitch (floats)
#define GEMM_SMEM ((2*128 + 2*64) * GP * sizeof(float))   // 55296 B

__global__ __launch_bounds__(256) void gemm_tc(
    const float* __restrict__ X, const float* __restrict__ W,
    const float* __restrict__ bias, float* __restrict__ C, int transposed)
{
    extern __shared__ float sm[];
    float* Xs[2] = { sm, sm + 128 * GP };
    float* Ws[2] = { sm + 256 * GP, sm + 256 * GP + 64 * GP };

    const int tid = threadIdx.x;
    const int L   = tid & 31;
    const int wid = tid >> 5;
    const int n0  = blockIdx.x * 128;
    const int m0  = blockIdx.y * 64;

    float c[8][4] = {};

    const int arow = wid * 16 + ((L >> 3) & 1) * 8 + (L & 7);
    const int acol = (L >> 4) * 4;
    const int brow = (L >> 4) * 8 + (L & 7);
    const int bcol = ((L >> 3) & 1) * 4;

    const int xrow = tid >> 3, xc4 = (tid & 7) * 4;   // + 32-row steps
    // prologue: tile 0
    #pragma unroll
    for (int r = 0; r < 4; r++)
        cp16(&Xs[0][(xrow + 32 * r) * GP + xc4],
             &X[(size_t)(n0 + xrow + 32 * r) * DIM + xc4]);
    #pragma unroll
    for (int r = 0; r < 2; r++)
        cp16(&Ws[0][(xrow + 32 * r) * GP + xc4],
             &W[(size_t)(m0 + xrow + 32 * r) * DIM + xc4]);
    CP_COMMIT();

    const int NK = DIM / 32;   // 16
    for (int t = 0; t < NK; t++) {
        int nb = (t + 1) & 1;
        if (t + 1 < NK) {
            int k0 = (t + 1) * 32;
            #pragma unroll
            for (int r = 0; r < 4; r++)
                cp16(&Xs[nb][(xrow + 32 * r) * GP + xc4],
                     &X[(size_t)(n0 + xrow + 32 * r) * DIM + k0 + xc4]);
            #pragma unroll
            for (int r = 0; r < 2; r++)
                cp16(&Ws[nb][(xrow + 32 * r) * GP + xc4],
                     &W[(size_t)(m0 + xrow + 32 * r) * DIM + k0 + xc4]);
        }
        CP_COMMIT();
        CP_WAIT1();
        __syncthreads();

        const float* Xb = Xs[t & 1];
        const float* Wb = Ws[t & 1];
        #pragma unroll
        for (int ks = 0; ks < 4; ks++) {
            uint32_t a[4];
            ldsm_x4(a, &Xb[arow * GP + ks * 8 + acol]);
            cvt4(a);
            #pragma unroll
            for (int jp = 0; jp < 4; jp++) {
                uint32_t b[4];
                ldsm_x4(b, &Wb[(jp * 16 + brow) * GP + ks * 8 + bcol]);
                cvt4(b);
                mma_tf32(c[jp * 2 + 0], a, b[0], b[1]);
                mma_tf32(c[jp * 2 + 1], a, b[2], b[3]);
            }
        }
        __syncthreads();
    }

    const int rlo  = n0 + wid * 16 + (L >> 2);
    const int colb = 2 * (L & 3);
    if (!transposed) {
        #pragma unroll
        for (int j = 0; j < 8; j++) {
            int col = m0 + j * 8 + colb;
            float b0 = bias[col], b1 = bias[col + 1];
            *(float2*)&C[(size_t)rlo * DIM + col] =
                make_float2(c[j][0] + b0, c[j][1] + b1);
            *(float2*)&C[(size_t)(rlo + 8) * DIM + col] =
                make_float2(c[j][2] + b0, c[j][3] + b1);
        }
    } else {
        int b_lo = rlo >> 12, t_lo = rlo & 4095;
        int rhi = rlo + 8;
        int b_hi = rhi >> 12, t_hi = rhi & 4095;
        #pragma unroll
        for (int j = 0; j < 8; j++) {
            int m = m0 + j * 8 + colb;
            float bb0 = bias[m], bb1 = bias[m + 1];
            C[(size_t)(b_lo * DIM + m)     * SEQ + t_lo] = c[j][0] + bb0;
            C[(size_t)(b_lo * DIM + m + 1) * SEQ + t_lo] = c[j][1] + bb1;
            C[(size_t)(b_hi * DIM + m)     * SEQ + t_hi] = c[j][2] + bb0;
            C[(size_t)(b_hi * DIM + m + 1) * SEQ + t_hi] = c[j][3] + bb1;
        }
    }
}

// ---------------------------------------------------------------------------
// Tensor-core flash attention, cp.async double-buffered K/V tiles.
// Grid (SEQ/128, HEADS, BATCH); block 256 (8 warps x 16 q-rows).
// ---------------------------------------------------------------------------
#define AP 68   // shared pitch (floats)
#define ATTN_SMEM ((128 + 4 * 64) * AP * sizeof(float))   // 104448 B

__global__ __launch_bounds__(256, 2) void attn_tc(
    const float* __restrict__ Q, const float* __restrict__ K,
    const float* __restrict__ Vt, float* __restrict__ O)
{
    extern __shared__ float sm[];
    float* QPs = sm;                                    // 128 x AP : Q then P
    float* Ksm[2] = { sm + 128 * AP, sm + 192 * AP };   // 64 x AP each
    float* Vsm[2] = { sm + 256 * AP, sm + 320 * AP };   // 64 x AP each

    const int tid = threadIdx.x;
    const int L   = tid & 31;
    const int wid = tid >> 5;
    const int q0  = blockIdx.x * 128;
    const int h   = blockIdx.y;
    const int b   = blockIdx.z;
    const size_t qk_base = (size_t)b * SEQ * DIM + (size_t)h * DQ;
    const size_t vt_base = (size_t)(b * DIM + h * DQ) * SEQ;

    const int lrow = tid >> 4, lc4 = (tid & 15) * 4;    // + 16-row steps

    // prologue: cp.async K/V tile 0 (raw fp32; tf32 rounding done on fragments)
    #pragma unroll
    for (int r = 0; r < 4; r++) {
        int row = lrow + 16 * r;
        cp16(&Ksm[0][row * AP + lc4], &K[qk_base + (size_t)row * DIM + lc4]);
        cp16(&Vsm[0][row * AP + lc4], &Vt[vt_base + (size_t)row * SEQ + lc4]);
    }
    CP_COMMIT();

    // Load Q tile (scaled by 1/sqrt(dq), tf32-rounded at STS)
    #pragma unroll
    for (int r = 0; r < 8; r++) {
        int e = tid + 256 * r;               // 2048 float4s
        int row = e >> 4, c4 = (e & 15) * 4;
        float4 v = *(const float4*)&Q[qk_base + (size_t)(q0 + row) * DIM + c4];
        v.x *= 0.125f; v.y *= 0.125f; v.z *= 0.125f; v.w *= 0.125f;
        sts_tf4(&QPs[row * AP + c4], v);
    }
    __syncthreads();

    const int arow = wid * 16 + ((L >> 3) & 1) * 8 + (L & 7);
    const int acol = (L >> 4) * 4;
    const int brow = (L >> 4) * 8 + (L & 7);
    const int bcol = ((L >> 3) & 1) * 4;

    uint32_t qf[8][4];
    #pragma unroll
    for (int ks = 0; ks < 8; ks++)
        ldsm_x4(qf[ks], &QPs[arow * AP + ks * 8 + acol]);

    float m_lo = -1e30f, m_hi = -1e30f, l_lo = 0.f, l_hi = 0.f;
    float o[8][4] = {};

    const int NT = SEQ / 64;   // 64-key tiles
    for (int t = 0; t < NT; t++) {
        // [A] prefetch tile t+1
        if (t + 1 < NT) {
            int nb = (t + 1) & 1;
            int k0 = (t + 1) * 64;
            #pragma unroll
            for (int r = 0; r < 4; r++) {
                int row = lrow + 16 * r;
                cp16(&Ksm[nb][row * AP + lc4],
                     &K[qk_base + (size_t)(k0 + row) * DIM + lc4]);
                cp16(&Vsm[nb][row * AP + lc4],
                     &Vt[vt_base + (size_t)row * SEQ + k0 + lc4]);
            }
        }
        CP_COMMIT();
        // [B] tile t resident
        CP_WAIT1();
        __syncthreads();

        const float* Kb = Ksm[t & 1];
        const float* Vb = Vsm[t & 1];

        // S = Q @ K^T  (16 rows x 64 keys per warp)
        float s[8][4] = {};
        #pragma unroll
        for (int ks = 0; ks < 8; ks++) {
            #pragma unroll
            for (int jp = 0; jp < 4; jp++) {
                uint32_t bf[4];
                ldsm_x4(bf, &Kb[(jp * 16 + brow) * AP + ks * 8 + bcol]);
                cvt4(bf);
                mma_tf32(s[jp * 2 + 0], qf[ks], bf[0], bf[1]);
                mma_tf32(s[jp * 2 + 1], qf[ks], bf[2], bf[3]);
            }
        }

        // Online softmax (rows: lo = base + L/4, hi = +8)
        float mx_lo = -1e30f, mx_hi = -1e30f;
        #pragma unroll
        for (int j = 0; j < 8; j++) {
            mx_lo = fmaxf(mx_lo, fmaxf(s[j][0], s[j][1]));
            mx_hi = fmaxf(mx_hi, fmaxf(s[j][2], s[j][3]));
        }
        mx_lo = fmaxf(mx_lo, __shfl_xor_sync(0xffffffffu, mx_lo, 1));
        mx_lo = fmaxf(mx_lo, __shfl_xor_sync(0xffffffffu, mx_lo, 2));
        mx_hi = fmaxf(mx_hi, __shfl_xor_sync(0xffffffffu, mx_hi, 1));
        mx_hi = fmaxf(mx_hi, __shfl_xor_sync(0xffffffffu, mx_hi, 2));

        float mn_lo = fmaxf(m_lo, mx_lo), mn_hi = fmaxf(m_hi, mx_hi);
        float al = __expf(m_lo - mn_lo),  ah = __expf(m_hi - mn_hi);
        m_lo = mn_lo; m_hi = mn_hi;

        float sum_lo = 0.f, sum_hi = 0.f;
        #pragma unroll
        for (int j = 0; j < 8; j++) {
            s[j][0] = __expf(s[j][0] - mn_lo);
            s[j][1] = __expf(s[j][1] - mn_lo);
            s[j][2] = __expf(s[j][2] - mn_hi);
            s[j][3] = __expf(s[j][3] - mn_hi);
            sum_lo += s[j][0] + s[j][1];
            sum_hi += s[j][2] + s[j][3];
        }
        sum_lo += __shfl_xor_sync(0xffffffffu, sum_lo, 1);
        sum_lo += __shfl_xor_sync(0xffffffffu, sum_lo, 2);
        sum_hi += __shfl_xor_sync(0xffffffffu, sum_hi, 1);
        sum_hi += __shfl_xor_sync(0xffffffffu, sum_hi, 2);
        l_lo = l_lo * al + sum_lo;
        l_hi = l_hi * ah + sum_hi;

        #pragma unroll
        for (int j = 0; j < 8; j++) {
            o[j][0] *= al; o[j][1] *= al;
            o[j][2] *= ah; o[j][3] *= ah;
        }

        // Store P (tf32) into warp-private rows of QPs
        const int prow = wid * 16 + (L >> 2);
        #pragma unroll
        for (int j = 0; j < 8; j++) {
            int col = j * 8 + 2 * (L & 3);
            *(float2*)&QPs[prow * AP + col] =
                make_float2(f2tf32f(s[j][0]), f2tf32f(s[j][1]));
            *(float2*)&QPs[(prow + 8) * AP + col] =
                make_float2(f2tf32f(s[j][2]), f2tf32f(s[j][3]));
        }
        __syncwarp();

        // O += P @ V  (B frags from Vt tile: B[k=key][n=dq] = Vsm[dq][key])
        #pragma unroll
        for (int ks = 0; ks < 8; ks++) {
            uint32_t a[4];
            ldsm_x4(a, &QPs[arow * AP + ks * 8 + acol]);
            #pragma unroll
            for (int jp = 0; jp < 4; jp++) {
                uint32_t bf[4];
                ldsm_x4(bf, &Vb[(jp * 16 + brow) * AP + ks * 8 + bcol]);
                cvt4(bf);
                mma_tf32(o[jp * 2 + 0], a, bf[0], bf[1]);
                mma_tf32(o[jp * 2 + 1], a, bf[2], bf[3]);
            }
        }
        // [D] all warps done reading buf[t&1] before iter t+1 overwrites buf[(t+2)&1]... 
        // (protects buf[(t+1)&1] readers of iter t-1 against cp.async of iter t+1)
        __syncthreads();
    }

    // Epilogue
    float il = 1.f / l_lo, ih = 1.f / l_hi;
    const int row = q0 + wid * 16 + (L >> 2);
    #pragma unroll
    for (int j = 0; j < 8; j++) {
        int col = j * 8 + 2 * (L & 3);
        *(float2*)&O[qk_base + (size_t)row * DIM + col] =
            make_float2(o[j][0] * il, o[j][1] * il);
        *(float2*)&O[qk_base + (size_t)(row + 8) * DIM + col] =
            make_float2(o[j][2] * ih, o[j][3] * ih);
    }
}

// ---------------------------------------------------------------------------
extern "C" void kernel_launch(void* const* d_in, const int* in_sizes, int n_in,
                              void* d_out, int out_size)
{
    const float* x  = (const float*)d_in[0];
    const float* Wq = (const float*)d_in[1];
    const float* bq = (const float*)d_in[2];
    const float* Wk = (const float*)d_in[3];
    const float* bk = (const float*)d_in[4];
    const float* Wv = (const float*)d_in[5];
    const float* bv = (const float*)d_in[6];
    const float* Wo = (const float*)d_in[7];
    const float* bo = (const float*)d_in[8];
    float* out = (float*)d_out;

    float *qp, *kp, *vtp, *aop;
    cudaGetSymbolAddress((void**)&qp,  g_q);
    cudaGetSymbolAddress((void**)&kp,  g_k);
    cudaGetSymbolAddress((void**)&vtp, g_vt);
    cudaGetSymbolAddress((void**)&aop, g_ao);

    cudaFuncSetAttribute(gemm_tc,
                         cudaFuncAttributeMaxDynamicSharedMemorySize,
                         (int)GEMM_SMEM);
    cudaFuncSetAttribute(attn_tc,
                         cudaFuncAttributeMaxDynamicSharedMemorySize,
                         (int)ATTN_SMEM);

    dim3 gridP(NTOK / 128, DIM / 64);   // 64 x 8

    gemm_tc<<<gridP, 256, GEMM_SMEM>>>(x, Wq, bq, qp, 0);
    gemm_tc<<<gridP, 256, GEMM_SMEM>>>(x, Wk, bk, kp, 0);
    gemm_tc<<<gridP, 256, GEMM_SMEM>>>(x, Wv, bv, vtp, 1);

    dim3 gridA(SEQ / 128, HEADS, BATCH);  // 32 x 8 x 2
    attn_tc<<<gridA, 256, ATTN_SMEM>>>(qp, kp, vtp, aop);

    gemm_tc<<<gridP, 256, GEMM_SMEM>>>(aop, Wo, bo, out, 0);
}

// round 6
// speedup vs baseline: 1.1417x; 1.1417x over previous
#include <cuda_runtime.h>
#include <math.h>
#include <stdint.h>

#define DIM   512
#define HEADS 8
#define DQ    64
#define SEQ   4096
#define BATCH 2
#define NTOK  (BATCH * SEQ)   // 8192

// Scratch (allocation-free rule: __device__ globals)
__device__ float g_q [NTOK * DIM];
__device__ float g_k [NTOK * DIM];
__device__ float g_vt[NTOK * DIM];   // V stored transposed: [b*512 + m][4096]
__device__ float g_ao[NTOK * DIM];

// ---------------------------------------------------------------------------
// helpers
// ---------------------------------------------------------------------------
__device__ __forceinline__ uint32_t f2tf32(float f) {
    uint32_t u; asm("cvt.rna.tf32.f32 %0, %1;" : "=r"(u) : "f"(f)); return u;
}
__device__ __forceinline__ float f2tf32f(float f) { return __uint_as_float(f2tf32(f)); }

__device__ __forceinline__ void sts_tf4(float* d, float4 v) {
    d[0] = f2tf32f(v.x); d[1] = f2tf32f(v.y);
    d[2] = f2tf32f(v.z); d[3] = f2tf32f(v.w);
}

__device__ __forceinline__ void ldsm_x4(uint32_t r[4], const float* p) {
    uint32_t a = (uint32_t)__cvta_generic_to_shared(p);
    asm volatile("ldmatrix.sync.aligned.m8n8.x4.shared.b16 {%0,%1,%2,%3}, [%4];"
                 : "=r"(r[0]), "=r"(r[1]), "=r"(r[2]), "=r"(r[3])
                 : "r"(a) : "memory");
}

// round raw fp32 fragment bits to tf32 in-register
__device__ __forceinline__ void cvt4(uint32_t r[4]) {
    #pragma unroll
    for (int i = 0; i < 4; i++)
        asm("cvt.rna.tf32.f32 %0, %0;" : "+r"(r[i]));
}

__device__ __forceinline__ void mma_tf32(float c[4], const uint32_t a[4],
                                         uint32_t b0, uint32_t b1) {
    asm volatile("mma.sync.aligned.m16n8k8.row.col.f32.tf32.tf32.f32 "
                 "{%0,%1,%2,%3}, {%4,%5,%6,%7}, {%8,%9}, {%0,%1,%2,%3};"
                 : "+f"(c[0]), "+f"(c[1]), "+f"(c[2]), "+f"(c[3])
                 : "r"(a[0]), "r"(a[1]), "r"(a[2]), "r"(a[3]), "r"(b0), "r"(b1));
}

__device__ __forceinline__ void cp16(float* smem_dst, const float* gsrc) {
    uint32_t a = (uint32_t)__cvta_generic_to_shared(smem_dst);
    asm volatile("cp.async.cg.shared.global [%0], [%1], 16;" :: "r"(a), "l"(gsrc));
}
#define CP_COMMIT() asm volatile("cp.async.commit_group;")
#define CP_WAIT1()  asm volatile("cp.async.wait_group 1;")

// ---------------------------------------------------------------------------
// Tensor-core GEMM: C[n,m] = sum_k X[n,k]*W[m,k] + bias[m]   (K = 512)
// CTA: 128 tokens x 64 cols.  8 warps.  cp.async double-buffered k-steps of 32.
// mode 0: plain fp32 out.  mode 1: tf32-rounded out (Q/K).
// mode 2: transposed + tf32-rounded out (V -> [b*512+m][4096]).
// ---------------------------------------------------------------------------
#define GP 36   // shared pitch (floats)
#define GEMM_SMEM ((2*128 + 2*64) * GP * sizeof(float))   // 55296 B

__global__ __launch_bounds__(256) void gemm_tc(
    const float* __restrict__ X, const float* __restrict__ W,
    const float* __restrict__ bias, float* __restrict__ C, int mode)
{
    extern __shared__ float sm[];
    float* Xs[2] = { sm, sm + 128 * GP };
    float* Ws[2] = { sm + 256 * GP, sm + 256 * GP + 64 * GP };

    const int tid = threadIdx.x;
    const int L   = tid & 31;
    const int wid = tid >> 5;
    const int n0  = blockIdx.x * 128;
    const int m0  = blockIdx.y * 64;

    float c[8][4] = {};

    const int arow = wid * 16 + ((L >> 3) & 1) * 8 + (L & 7);
    const int acol = (L >> 4) * 4;
    const int brow = (L >> 4) * 8 + (L & 7);
    const int bcol = ((L >> 3) & 1) * 4;

    const int xrow = tid >> 3, xc4 = (tid & 7) * 4;   // + 32-row steps
    // prologue: tile 0
    #pragma unroll
    for (int r = 0; r < 4; r++)
        cp16(&Xs[0][(xrow + 32 * r) * GP + xc4],
             &X[(size_t)(n0 + xrow + 32 * r) * DIM + xc4]);
    #pragma unroll
    for (int r = 0; r < 2; r++)
        cp16(&Ws[0][(xrow + 32 * r) * GP + xc4],
             &W[(size_t)(m0 + xrow + 32 * r) * DIM + xc4]);
    CP_COMMIT();

    const int NK = DIM / 32;   // 16
    for (int t = 0; t < NK; t++) {
        int nb = (t + 1) & 1;
        if (t + 1 < NK) {
            int k0 = (t + 1) * 32;
            #pragma unroll
            for (int r = 0; r < 4; r++)
                cp16(&Xs[nb][(xrow + 32 * r) * GP + xc4],
                     &X[(size_t)(n0 + xrow + 32 * r) * DIM + k0 + xc4]);
            #pragma unroll
            for (int r = 0; r < 2; r++)
                cp16(&Ws[nb][(xrow + 32 * r) * GP + xc4],
                     &W[(size_t)(m0 + xrow + 32 * r) * DIM + k0 + xc4]);
        }
        CP_COMMIT();
        CP_WAIT1();
        __syncthreads();

        const float* Xb = Xs[t & 1];
        const float* Wb = Ws[t & 1];
        #pragma unroll
        for (int ks = 0; ks < 4; ks++) {
            uint32_t a[4];
            ldsm_x4(a, &Xb[arow * GP + ks * 8 + acol]);
            cvt4(a);
            #pragma unroll
            for (int jp = 0; jp < 4; jp++) {
                uint32_t b[4];
                ldsm_x4(b, &Wb[(jp * 16 + brow) * GP + ks * 8 + bcol]);
                cvt4(b);
                mma_tf32(c[jp * 2 + 0], a, b[0], b[1]);
                mma_tf32(c[jp * 2 + 1], a, b[2], b[3]);
            }
        }
        __syncthreads();
    }

    const int rlo  = n0 + wid * 16 + (L >> 2);
    const int colb = 2 * (L & 3);
    if (mode == 0) {
        #pragma unroll
        for (int j = 0; j < 8; j++) {
            int col = m0 + j * 8 + colb;
            float b0 = bias[col], b1 = bias[col + 1];
            *(float2*)&C[(size_t)rlo * DIM + col] =
                make_float2(c[j][0] + b0, c[j][1] + b1);
            *(float2*)&C[(size_t)(rlo + 8) * DIM + col] =
                make_float2(c[j][2] + b0, c[j][3] + b1);
        }
    } else if (mode == 1) {
        #pragma unroll
        for (int j = 0; j < 8; j++) {
            int col = m0 + j * 8 + colb;
            float b0 = bias[col], b1 = bias[col + 1];
            *(float2*)&C[(size_t)rlo * DIM + col] =
                make_float2(f2tf32f(c[j][0] + b0), f2tf32f(c[j][1] + b1));
            *(float2*)&C[(size_t)(rlo + 8) * DIM + col] =
                make_float2(f2tf32f(c[j][2] + b0), f2tf32f(c[j][3] + b1));
        }
    } else {
        int b_lo = rlo >> 12, t_lo = rlo & 4095;
        int rhi = rlo + 8;
        int b_hi = rhi >> 12, t_hi = rhi & 4095;
        #pragma unroll
        for (int j = 0; j < 8; j++) {
            int m = m0 + j * 8 + colb;
            float bb0 = bias[m], bb1 = bias[m + 1];
            C[(size_t)(b_lo * DIM + m)     * SEQ + t_lo] = f2tf32f(c[j][0] + bb0);
            C[(size_t)(b_lo * DIM + m + 1) * SEQ + t_lo] = f2tf32f(c[j][1] + bb1);
            C[(size_t)(b_hi * DIM + m)     * SEQ + t_hi] = f2tf32f(c[j][2] + bb0);
            C[(size_t)(b_hi * DIM + m + 1) * SEQ + t_hi] = f2tf32f(c[j][3] + bb1);
        }
    }
}

// ---------------------------------------------------------------------------
// Tensor-core flash attention, cp.async double-buffered K/V tiles.
// Inputs are pre-rounded tf32 bits -> NO in-loop conversion.
// Grid (SEQ/128, HEADS, BATCH); block 256 (8 warps x 16 q-rows).
// ---------------------------------------------------------------------------
#define AP 68   // shared pitch (floats)
#define ATTN_SMEM ((128 + 4 * 64) * AP * sizeof(float))   // 104448 B

__global__ __launch_bounds__(256, 2) void attn_tc(
    const float* __restrict__ Q, const float* __restrict__ K,
    const float* __restrict__ Vt, float* __restrict__ O)
{
    extern __shared__ float sm[];
    float* QPs = sm;                                    // 128 x AP : Q then P
    float* Ksm[2] = { sm + 128 * AP, sm + 192 * AP };   // 64 x AP each
    float* Vsm[2] = { sm + 256 * AP, sm + 320 * AP };   // 64 x AP each

    const int tid = threadIdx.x;
    const int L   = tid & 31;
    const int wid = tid >> 5;
    const int q0  = blockIdx.x * 128;
    const int h   = blockIdx.y;
    const int b   = blockIdx.z;
    const size_t qk_base = (size_t)b * SEQ * DIM + (size_t)h * DQ;
    const size_t vt_base = (size_t)(b * DIM + h * DQ) * SEQ;

    const int lrow = tid >> 4, lc4 = (tid & 15) * 4;    // + 16-row steps

    // prologue: cp.async K/V tile 0 (already tf32 bits)
    #pragma unroll
    for (int r = 0; r < 4; r++) {
        int row = lrow + 16 * r;
        cp16(&Ksm[0][row * AP + lc4], &K[qk_base + (size_t)row * DIM + lc4]);
        cp16(&Vsm[0][row * AP + lc4], &Vt[vt_base + (size_t)row * SEQ + lc4]);
    }
    CP_COMMIT();

    // Load Q tile (already tf32; scale by 1/8 = exact power of two)
    #pragma unroll
    for (int r = 0; r < 8; r++) {
        int e = tid + 256 * r;               // 2048 float4s
        int row = e >> 4, c4 = (e & 15) * 4;
        float4 v = *(const float4*)&Q[qk_base + (size_t)(q0 + row) * DIM + c4];
        QPs[row * AP + c4 + 0] = v.x * 0.125f;
        QPs[row * AP + c4 + 1] = v.y * 0.125f;
        QPs[row * AP + c4 + 2] = v.z * 0.125f;
        QPs[row * AP + c4 + 3] = v.w * 0.125f;
    }
    __syncthreads();

    const int arow = wid * 16 + ((L >> 3) & 1) * 8 + (L & 7);
    const int acol = (L >> 4) * 4;
    const int brow = (L >> 4) * 8 + (L & 7);
    const int bcol = ((L >> 3) & 1) * 4;

    uint32_t qf[8][4];
    #pragma unroll
    for (int ks = 0; ks < 8; ks++)
        ldsm_x4(qf[ks], &QPs[arow * AP + ks * 8 + acol]);

    float m_lo = -1e30f, m_hi = -1e30f, l_lo = 0.f, l_hi = 0.f;
    float o[8][4] = {};

    const int NT = SEQ / 64;   // 64-key tiles
    for (int t = 0; t < NT; t++) {
        // prefetch tile t+1
        if (t + 1 < NT) {
            int nb = (t + 1) & 1;
            int k0 = (t + 1) * 64;
            #pragma unroll
            for (int r = 0; r < 4; r++) {
                int row = lrow + 16 * r;
                cp16(&Ksm[nb][row * AP + lc4],
                     &K[qk_base + (size_t)(k0 + row) * DIM + lc4]);
                cp16(&Vsm[nb][row * AP + lc4],
                     &Vt[vt_base + (size_t)row * SEQ + k0 + lc4]);
            }
        }
        CP_COMMIT();
        CP_WAIT1();
        __syncthreads();

        const float* Kb = Ksm[t & 1];
        const float* Vb = Vsm[t & 1];

        // S = Q @ K^T  (16 rows x 64 keys per warp)
        float s[8][4] = {};
        #pragma unroll
        for (int ks = 0; ks < 8; ks++) {
            #pragma unroll
            for (int jp = 0; jp < 4; jp++) {
                uint32_t bf[4];
                ldsm_x4(bf, &Kb[(jp * 16 + brow) * AP + ks * 8 + bcol]);
                mma_tf32(s[jp * 2 + 0], qf[ks], bf[0], bf[1]);
                mma_tf32(s[jp * 2 + 1], qf[ks], bf[2], bf[3]);
            }
        }

        // Online softmax (rows: lo = base + L/4, hi = +8)
        float mx_lo = -1e30f, mx_hi = -1e30f;
        #pragma unroll
        for (int j = 0; j < 8; j++) {
            mx_lo = fmaxf(mx_lo, fmaxf(s[j][0], s[j][1]));
            mx_hi = fmaxf(mx_hi, fmaxf(s[j][2], s[j][3]));
        }
        mx_lo = fmaxf(mx_lo, __shfl_xor_sync(0xffffffffu, mx_lo, 1));
        mx_lo = fmaxf(mx_lo, __shfl_xor_sync(0xffffffffu, mx_lo, 2));
        mx_hi = fmaxf(mx_hi, __shfl_xor_sync(0xffffffffu, mx_hi, 1));
        mx_hi = fmaxf(mx_hi, __shfl_xor_sync(0xffffffffu, mx_hi, 2));

        float mn_lo = fmaxf(m_lo, mx_lo), mn_hi = fmaxf(m_hi, mx_hi);
        float al = __expf(m_lo - mn_lo),  ah = __expf(m_hi - mn_hi);
        m_lo = mn_lo; m_hi = mn_hi;

        float sum_lo = 0.f, sum_hi = 0.f;
        #pragma unroll
        for (int j = 0; j < 8; j++) {
            s[j][0] = __expf(s[j][0] - mn_lo);
            s[j][1] = __expf(s[j][1] - mn_lo);
            s[j][2] = __expf(s[j][2] - mn_hi);
            s[j][3] = __expf(s[j][3] - mn_hi);
            sum_lo += s[j][0] + s[j][1];
            sum_hi += s[j][2] + s[j][3];
        }
        sum_lo += __shfl_xor_sync(0xffffffffu, sum_lo, 1);
        sum_lo += __shfl_xor_sync(0xffffffffu, sum_lo, 2);
        sum_hi += __shfl_xor_sync(0xffffffffu, sum_hi, 1);
        sum_hi += __shfl_xor_sync(0xffffffffu, sum_hi, 2);
        l_lo = l_lo * al + sum_lo;
        l_hi = l_hi * ah + sum_hi;

        #pragma unroll
        for (int j = 0; j < 8; j++) {
            o[j][0] *= al; o[j][1] *= al;
            o[j][2] *= ah; o[j][3] *= ah;
        }

        // Store P (tf32) into warp-private rows of QPs
        const int prow = wid * 16 + (L >> 2);
        #pragma unroll
        for (int j = 0; j < 8; j++) {
            int col = j * 8 + 2 * (L & 3);
            *(float2*)&QPs[prow * AP + col] =
                make_float2(f2tf32f(s[j][0]), f2tf32f(s[j][1]));
            *(float2*)&QPs[(prow + 8) * AP + col] =
                make_float2(f2tf32f(s[j][2]), f2tf32f(s[j][3]));
        }
        __syncwarp();

        // O += P @ V  (B frags from Vt tile: B[k=key][n=dq] = Vsm[dq][key])
        #pragma unroll
        for (int ks = 0; ks < 8; ks++) {
            uint32_t a[4];
            ldsm_x4(a, &QPs[arow * AP + ks * 8 + acol]);
            #pragma unroll
            for (int jp = 0; jp < 4; jp++) {
                uint32_t bf[4];
                ldsm_x4(bf, &Vb[(jp * 16 + brow) * AP + ks * 8 + bcol]);
                mma_tf32(o[jp * 2 + 0], a, bf[0], bf[1]);
                mma_tf32(o[jp * 2 + 1], a, bf[2], bf[3]);
            }
        }
        __syncthreads();   // protect buffers before next prefetch/overwrite
    }

    // Epilogue
    float il = 1.f / l_lo, ih = 1.f / l_hi;
    const int row = q0 + wid * 16 + (L >> 2);
    #pragma unroll
    for (int j = 0; j < 8; j++) {
        int col = j * 8 + 2 * (L & 3);
        *(float2*)&O[qk_base + (size_t)row * DIM + col] =
            make_float2(o[j][0] * il, o[j][1] * il);
        *(float2*)&O[qk_base + (size_t)(row + 8) * DIM + col] =
            make_float2(o[j][2] * ih, o[j][3] * ih);
    }
}

// ---------------------------------------------------------------------------
extern "C" void kernel_launch(void* const* d_in, const int* in_sizes, int n_in,
                              void* d_out, int out_size)
{
    const float* x  = (const float*)d_in[0];
    const float* Wq = (const float*)d_in[1];
    const float* bq = (const float*)d_in[2];
    const float* Wk = (const float*)d_in[3];
    const float* bk = (const float*)d_in[4];
    const float* Wv = (const float*)d_in[5];
    const float* bv = (const float*)d_in[6];
    const float* Wo = (const float*)d_in[7];
    const float* bo = (const float*)d_in[8];
    float* out = (float*)d_out;

    float *qp, *kp, *vtp, *aop;
    cudaGetSymbolAddress((void**)&qp,  g_q);
    cudaGetSymbolAddress((void**)&kp,  g_k);
    cudaGetSymbolAddress((void**)&vtp, g_vt);
    cudaGetSymbolAddress((void**)&aop, g_ao);

    cudaFuncSetAttribute(gemm_tc,
                         cudaFuncAttributeMaxDynamicSharedMemorySize,
                         (int)GEMM_SMEM);
    cudaFuncSetAttribute(attn_tc,
                         cudaFuncAttributeMaxDynamicSharedMemorySize,
                         (int)ATTN_SMEM);

    dim3 gridP(NTOK / 128, DIM / 64);   // 64 x 8

    gemm_tc<<<gridP, 256, GEMM_SMEM>>>(x, Wq, bq, qp, 1);
    gemm_tc<<<gridP, 256, GEMM_SMEM>>>(x, Wk, bk, kp, 1);
    gemm_tc<<<gridP, 256, GEMM_SMEM>>>(x, Wv, bv, vtp, 2);

    dim3 gridA(SEQ / 128, HEADS, BATCH);  // 32 x 8 x 2
    attn_tc<<<gridA, 256, ATTN_SMEM>>>(qp, kp, vtp, aop);

    gemm_tc<<<gridP, 256, GEMM_SMEM>>>(aop, Wo, bo, out, 0);
}

// round 7
// speedup vs baseline: 1.3955x; 1.2222x over previous
#include <cuda_runtime.h>
#include <cuda_bf16.h>
#include <math.h>
#include <stdint.h>

#define DIM   512
#define HEADS 8
#define DQ    64
#define SEQ   4096
#define BATCH 2
#define NTOK  (BATCH * SEQ)   // 8192

// Scratch (allocation-free rule: __device__ globals)
__device__ float g_q [NTOK * DIM];
__device__ float g_k [NTOK * DIM];
__device__ __nv_bfloat16 g_vt[NTOK * DIM];   // V transposed bf16: [b*512+m][4096]
__device__ float g_ao[NTOK * DIM];

// ---------------------------------------------------------------------------
// helpers
// ---------------------------------------------------------------------------
__device__ __forceinline__ uint32_t f2tf32(float f) {
    uint32_t u; asm("cvt.rna.tf32.f32 %0, %1;" : "=r"(u) : "f"(f)); return u;
}
__device__ __forceinline__ float f2tf32f(float f) { return __uint_as_float(f2tf32(f)); }

__device__ __forceinline__ uint32_t pack_bf16(float lo, float hi) {
    uint32_t r; asm("cvt.rn.bf16x2.f32 %0, %1, %2;" : "=r"(r) : "f"(hi), "f"(lo));
    return r;
}

__device__ __forceinline__ void ldsm_x4(uint32_t r[4], const float* p) {
    uint32_t a = (uint32_t)__cvta_generic_to_shared(p);
    asm volatile("ldmatrix.sync.aligned.m8n8.x4.shared.b16 {%0,%1,%2,%3}, [%4];"
                 : "=r"(r[0]), "=r"(r[1]), "=r"(r[2]), "=r"(r[3])
                 : "r"(a) : "memory");
}
__device__ __forceinline__ void ldsm_x4b(uint32_t r[4], const __nv_bfloat16* p) {
    uint32_t a = (uint32_t)__cvta_generic_to_shared(p);
    asm volatile("ldmatrix.sync.aligned.m8n8.x4.shared.b16 {%0,%1,%2,%3}, [%4];"
                 : "=r"(r[0]), "=r"(r[1]), "=r"(r[2]), "=r"(r[3])
                 : "r"(a) : "memory");
}

// round raw fp32 fragment bits to tf32 in-register
__device__ __forceinline__ void cvt4(uint32_t r[4]) {
    #pragma unroll
    for (int i = 0; i < 4; i++)
        asm("cvt.rna.tf32.f32 %0, %0;" : "+r"(r[i]));
}

__device__ __forceinline__ void mma_tf32(float c[4], const uint32_t a[4],
                                         uint32_t b0, uint32_t b1) {
    asm volatile("mma.sync.aligned.m16n8k8.row.col.f32.tf32.tf32.f32 "
                 "{%0,%1,%2,%3}, {%4,%5,%6,%7}, {%8,%9}, {%0,%1,%2,%3};"
                 : "+f"(c[0]), "+f"(c[1]), "+f"(c[2]), "+f"(c[3])
                 : "r"(a[0]), "r"(a[1]), "r"(a[2]), "r"(a[3]), "r"(b0), "r"(b1));
}

__device__ __forceinline__ void mma_bf16(float c[4], const uint32_t a[4],
                                         uint32_t b0, uint32_t b1) {
    asm volatile("mma.sync.aligned.m16n8k16.row.col.f32.bf16.bf16.f32 "
                 "{%0,%1,%2,%3}, {%4,%5,%6,%7}, {%8,%9}, {%0,%1,%2,%3};"
                 : "+f"(c[0]), "+f"(c[1]), "+f"(c[2]), "+f"(c[3])
                 : "r"(a[0]), "r"(a[1]), "r"(a[2]), "r"(a[3]), "r"(b0), "r"(b1));
}

__device__ __forceinline__ void cp16(float* smem_dst, const float* gsrc) {
    uint32_t a = (uint32_t)__cvta_generic_to_shared(smem_dst);
    asm volatile("cp.async.cg.shared.global [%0], [%1], 16;" :: "r"(a), "l"(gsrc));
}
__device__ __forceinline__ void cp16b(__nv_bfloat16* smem_dst, const __nv_bfloat16* gsrc) {
    uint32_t a = (uint32_t)__cvta_generic_to_shared(smem_dst);
    asm volatile("cp.async.cg.shared.global [%0], [%1], 16;" :: "r"(a), "l"(gsrc));
}
#define CP_COMMIT() asm volatile("cp.async.commit_group;")
#define CP_WAIT1()  asm volatile("cp.async.wait_group 1;")

// ---------------------------------------------------------------------------
// Tensor-core GEMM: C[n,m] = sum_k X[n,k]*W[m,k] + bias[m]   (K = 512)
// CTA: 128 tokens x 64 cols.  8 warps.  cp.async double-buffered k-steps of 32.
// mode 0: plain fp32 out.  mode 1: tf32-rounded out (Q/K).
// mode 2: transposed bf16 out (V -> [b*512+m][4096]).
// ---------------------------------------------------------------------------
#define GP 36   // shared pitch (floats)
#define GEMM_SMEM ((2*128 + 2*64) * GP * sizeof(float))   // 55296 B

__global__ __launch_bounds__(256) void gemm_tc(
    const float* __restrict__ X, const float* __restrict__ W,
    const float* __restrict__ bias, float* __restrict__ C, int mode)
{
    extern __shared__ float sm[];
    float* Xs[2] = { sm, sm + 128 * GP };
    float* Ws[2] = { sm + 256 * GP, sm + 256 * GP + 64 * GP };

    const int tid = threadIdx.x;
    const int L   = tid & 31;
    const int wid = tid >> 5;
    const int n0  = blockIdx.x * 128;
    const int m0  = blockIdx.y * 64;

    float c[8][4] = {};

    const int arow = wid * 16 + ((L >> 3) & 1) * 8 + (L & 7);
    const int acol = (L >> 4) * 4;
    const int brow = (L >> 4) * 8 + (L & 7);
    const int bcol = ((L >> 3) & 1) * 4;

    const int xrow = tid >> 3, xc4 = (tid & 7) * 4;   // + 32-row steps
    #pragma unroll
    for (int r = 0; r < 4; r++)
        cp16(&Xs[0][(xrow + 32 * r) * GP + xc4],
             &X[(size_t)(n0 + xrow + 32 * r) * DIM + xc4]);
    #pragma unroll
    for (int r = 0; r < 2; r++)
        cp16(&Ws[0][(xrow + 32 * r) * GP + xc4],
             &W[(size_t)(m0 + xrow + 32 * r) * DIM + xc4]);
    CP_COMMIT();

    const int NK = DIM / 32;   // 16
    for (int t = 0; t < NK; t++) {
        int nb = (t + 1) & 1;
        if (t + 1 < NK) {
            int k0 = (t + 1) * 32;
            #pragma unroll
            for (int r = 0; r < 4; r++)
                cp16(&Xs[nb][(xrow + 32 * r) * GP + xc4],
                     &X[(size_t)(n0 + xrow + 32 * r) * DIM + k0 + xc4]);
            #pragma unroll
            for (int r = 0; r < 2; r++)
                cp16(&Ws[nb][(xrow + 32 * r) * GP + xc4],
                     &W[(size_t)(m0 + xrow + 32 * r) * DIM + k0 + xc4]);
        }
        CP_COMMIT();
        CP_WAIT1();
        __syncthreads();

        const float* Xb = Xs[t & 1];
        const float* Wb = Ws[t & 1];
        #pragma unroll
        for (int ks = 0; ks < 4; ks++) {
            uint32_t a[4];
            ldsm_x4(a, &Xb[arow * GP + ks * 8 + acol]);
            cvt4(a);
            #pragma unroll
            for (int jp = 0; jp < 4; jp++) {
                uint32_t b[4];
                ldsm_x4(b, &Wb[(jp * 16 + brow) * GP + ks * 8 + bcol]);
                cvt4(b);
                mma_tf32(c[jp * 2 + 0], a, b[0], b[1]);
                mma_tf32(c[jp * 2 + 1], a, b[2], b[3]);
            }
        }
        __syncthreads();
    }

    const int rlo  = n0 + wid * 16 + (L >> 2);
    const int colb = 2 * (L & 3);
    if (mode == 0) {
        #pragma unroll
        for (int j = 0; j < 8; j++) {
            int col = m0 + j * 8 + colb;
            float b0 = bias[col], b1 = bias[col + 1];
            *(float2*)&C[(size_t)rlo * DIM + col] =
                make_float2(c[j][0] + b0, c[j][1] + b1);
            *(float2*)&C[(size_t)(rlo + 8) * DIM + col] =
                make_float2(c[j][2] + b0, c[j][3] + b1);
        }
    } else if (mode == 1) {
        #pragma unroll
        for (int j = 0; j < 8; j++) {
            int col = m0 + j * 8 + colb;
            float b0 = bias[col], b1 = bias[col + 1];
            *(float2*)&C[(size_t)rlo * DIM + col] =
                make_float2(f2tf32f(c[j][0] + b0), f2tf32f(c[j][1] + b1));
            *(float2*)&C[(size_t)(rlo + 8) * DIM + col] =
                make_float2(f2tf32f(c[j][2] + b0), f2tf32f(c[j][3] + b1));
        }
    } else {
        __nv_bfloat16* Cb = (__nv_bfloat16*)C;
        int b_lo = rlo >> 12, t_lo = rlo & 4095;
        int rhi = rlo + 8;
        int b_hi = rhi >> 12, t_hi = rhi & 4095;
        #pragma unroll
        for (int j = 0; j < 8; j++) {
            int m = m0 + j * 8 + colb;
            float bb0 = bias[m], bb1 = bias[m + 1];
            Cb[(size_t)(b_lo * DIM + m)     * SEQ + t_lo] = __float2bfloat16(c[j][0] + bb0);
            Cb[(size_t)(b_lo * DIM + m + 1) * SEQ + t_lo] = __float2bfloat16(c[j][1] + bb1);
            Cb[(size_t)(b_hi * DIM + m)     * SEQ + t_hi] = __float2bfloat16(c[j][2] + bb0);
            Cb[(size_t)(b_hi * DIM + m + 1) * SEQ + t_hi] = __float2bfloat16(c[j][3] + bb1);
        }
    }
}

// ---------------------------------------------------------------------------
// Flash attention: QK in tf32, PV in bf16 with register-resident P.
// Grid (SEQ/128, HEADS, BATCH); block 256 (8 warps x 16 q-rows).
// ---------------------------------------------------------------------------
#define AP  68   // fp32 shared pitch (Q/K)
#define VPB 72   // bf16 shared pitch (V)
#define ATTN_SMEM (256 * AP * 4 + 2 * 64 * VPB * 2)   // 69632 + 18432 = 88064 B

__global__ __launch_bounds__(256, 2) void attn_tc(
    const float* __restrict__ Q, const float* __restrict__ K,
    const __nv_bfloat16* __restrict__ Vt, float* __restrict__ O)
{
    extern __shared__ float sm[];
    float* Qsm = sm;                                    // 128 x AP
    float* Ksm[2] = { sm + 128 * AP, sm + 192 * AP };   // 64 x AP each
    __nv_bfloat16* Vbase = (__nv_bfloat16*)(sm + 256 * AP);
    __nv_bfloat16* Vsm[2] = { Vbase, Vbase + 64 * VPB };  // 64(dq) x VPB(keys)

    const int tid = threadIdx.x;
    const int L   = tid & 31;
    const int wid = tid >> 5;
    const int q0  = blockIdx.x * 128;
    const int h   = blockIdx.y;
    const int b   = blockIdx.z;
    const size_t qk_base = (size_t)b * SEQ * DIM + (size_t)h * DQ;
    const size_t vt_base = (size_t)(b * DIM + h * DQ) * SEQ;

    const int lrow = tid >> 4, lc4 = (tid & 15) * 4;    // K loads (+16-row steps)
    const int vrow = tid >> 2, vc8 = (tid & 3) * 8;     // V loads (chunks vc8, vc8+32)

    // prologue: cp.async K/V tile 0
    #pragma unroll
    for (int r = 0; r < 4; r++) {
        int row = lrow + 16 * r;
        cp16(&Ksm[0][row * AP + lc4], &K[qk_base + (size_t)row * DIM + lc4]);
    }
    cp16b(&Vsm[0][vrow * VPB + vc8],      &Vt[vt_base + (size_t)vrow * SEQ + vc8]);
    cp16b(&Vsm[0][vrow * VPB + vc8 + 32], &Vt[vt_base + (size_t)vrow * SEQ + vc8 + 32]);
    CP_COMMIT();

    // Load Q tile (already tf32; scale by 1/8 = exact power of two)
    #pragma unroll
    for (int r = 0; r < 8; r++) {
        int e = tid + 256 * r;
        int row = e >> 4, c4 = (e & 15) * 4;
        float4 v = *(const float4*)&Q[qk_base + (size_t)(q0 + row) * DIM + c4];
        Qsm[row * AP + c4 + 0] = v.x * 0.125f;
        Qsm[row * AP + c4 + 1] = v.y * 0.125f;
        Qsm[row * AP + c4 + 2] = v.z * 0.125f;
        Qsm[row * AP + c4 + 3] = v.w * 0.125f;
    }
    __syncthreads();

    const int arow = wid * 16 + ((L >> 3) & 1) * 8 + (L & 7);
    const int acol = (L >> 4) * 4;
    const int brow = (L >> 4) * 8 + (L & 7);
    const int bcol = ((L >> 3) & 1) * 4;
    // V ldsm lane mapping: 4 tiles along keys (k32 per x4)
    const int vlrow = L & 7;
    const int vlcol = ((L >> 3) & 1) * 8 + ((L >> 4) & 1) * 16;

    uint32_t qf[8][4];
    #pragma unroll
    for (int ks = 0; ks < 8; ks++)
        ldsm_x4(qf[ks], &Qsm[arow * AP + ks * 8 + acol]);

    float m_lo = -1e30f, m_hi = -1e30f, l_lo = 0.f, l_hi = 0.f;
    float o[8][4] = {};

    const int NT = SEQ / 64;
    for (int t = 0; t < NT; t++) {
        // prefetch tile t+1
        if (t + 1 < NT) {
            int nb = (t + 1) & 1;
            int k0 = (t + 1) * 64;
            #pragma unroll
            for (int r = 0; r < 4; r++) {
                int row = lrow + 16 * r;
                cp16(&Ksm[nb][row * AP + lc4],
                     &K[qk_base + (size_t)(k0 + row) * DIM + lc4]);
            }
            cp16b(&Vsm[nb][vrow * VPB + vc8],
                  &Vt[vt_base + (size_t)vrow * SEQ + k0 + vc8]);
            cp16b(&Vsm[nb][vrow * VPB + vc8 + 32],
                  &Vt[vt_base + (size_t)vrow * SEQ + k0 + vc8 + 32]);
        }
        CP_COMMIT();
        CP_WAIT1();
        __syncthreads();

        const float* Kb = Ksm[t & 1];
        const __nv_bfloat16* Vb = Vsm[t & 1];

        // S = Q @ K^T  (tf32; 16 rows x 64 keys per warp)
        float s[8][4] = {};
        #pragma unroll
        for (int ks = 0; ks < 8; ks++) {
            #pragma unroll
            for (int jp = 0; jp < 4; jp++) {
                uint32_t bf[4];
                ldsm_x4(bf, &Kb[(jp * 16 + brow) * AP + ks * 8 + bcol]);
                mma_tf32(s[jp * 2 + 0], qf[ks], bf[0], bf[1]);
                mma_tf32(s[jp * 2 + 1], qf[ks], bf[2], bf[3]);
            }
        }

        // Online softmax (rows: lo = L/4, hi = +8)
        float mx_lo = -1e30f, mx_hi = -1e30f;
        #pragma unroll
        for (int j = 0; j < 8; j++) {
            mx_lo = fmaxf(mx_lo, fmaxf(s[j][0], s[j][1]));
            mx_hi = fmaxf(mx_hi, fmaxf(s[j][2], s[j][3]));
        }
        mx_lo = fmaxf(mx_lo, __shfl_xor_sync(0xffffffffu, mx_lo, 1));
        mx_lo = fmaxf(mx_lo, __shfl_xor_sync(0xffffffffu, mx_lo, 2));
        mx_hi = fmaxf(mx_hi, __shfl_xor_sync(0xffffffffu, mx_hi, 1));
        mx_hi = fmaxf(mx_hi, __shfl_xor_sync(0xffffffffu, mx_hi, 2));

        float mn_lo = fmaxf(m_lo, mx_lo), mn_hi = fmaxf(m_hi, mx_hi);
        float al = __expf(m_lo - mn_lo),  ah = __expf(m_hi - mn_hi);
        m_lo = mn_lo; m_hi = mn_hi;

        float sum_lo = 0.f, sum_hi = 0.f;
        #pragma unroll
        for (int j = 0; j < 8; j++) {
            s[j][0] = __expf(s[j][0] - mn_lo);
            s[j][1] = __expf(s[j][1] - mn_lo);
            s[j][2] = __expf(s[j][2] - mn_hi);
            s[j][3] = __expf(s[j][3] - mn_hi);
            sum_lo += s[j][0] + s[j][1];
            sum_hi += s[j][2] + s[j][3];
        }
        sum_lo += __shfl_xor_sync(0xffffffffu, sum_lo, 1);
        sum_lo += __shfl_xor_sync(0xffffffffu, sum_lo, 2);
        sum_hi += __shfl_xor_sync(0xffffffffu, sum_hi, 1);
        sum_hi += __shfl_xor_sync(0xffffffffu, sum_hi, 2);
        l_lo = l_lo * al + sum_lo;
        l_hi = l_hi * ah + sum_hi;

        #pragma unroll
        for (int j = 0; j < 8; j++) {
            o[j][0] *= al; o[j][1] *= al;
            o[j][2] *= ah; o[j][3] *= ah;
        }

        // Pack P into bf16 A-fragments IN REGISTERS (no smem round-trip).
        // kb-th k16 block: p[kb*4..] = {rowsLo/k-even-block, rowsHi, rowsLo/k-odd-block, rowsHi}
        uint32_t p[16];
        #pragma unroll
        for (int kb = 0; kb < 4; kb++) {
            p[kb * 4 + 0] = pack_bf16(s[2 * kb][0],     s[2 * kb][1]);
            p[kb * 4 + 1] = pack_bf16(s[2 * kb][2],     s[2 * kb][3]);
            p[kb * 4 + 2] = pack_bf16(s[2 * kb + 1][0], s[2 * kb + 1][1]);
            p[kb * 4 + 3] = pack_bf16(s[2 * kb + 1][2], s[2 * kb + 1][3]);
        }

        // O += P @ V  (bf16 m16n8k16; B frags from Vsm[dq][key])
        #pragma unroll
        for (int m2 = 0; m2 < 2; m2++) {
            #pragma unroll
            for (int jp = 0; jp < 8; jp++) {
                uint32_t bf[4];
                ldsm_x4b(bf, &Vb[(jp * 8 + vlrow) * VPB + m2 * 32 + vlcol]);
                mma_bf16(o[jp], &p[(2 * m2) * 4],     bf[0], bf[1]);
                mma_bf16(o[jp], &p[(2 * m2 + 1) * 4], bf[2], bf[3]);
            }
        }
        __syncthreads();   // protect buffers before next prefetch overwrite
    }

    // Epilogue
    float il = 1.f / l_lo, ih = 1.f / l_hi;
    const int row = q0 + wid * 16 + (L >> 2);
    #pragma unroll
    for (int j = 0; j < 8; j++) {
        int col = j * 8 + 2 * (L & 3);
        *(float2*)&O[qk_base + (size_t)row * DIM + col] =
            make_float2(o[j][0] * il, o[j][1] * il);
        *(float2*)&O[qk_base + (size_t)(row + 8) * DIM + col] =
            make_float2(o[j][2] * ih, o[j][3] * ih);
    }
}

// ---------------------------------------------------------------------------
extern "C" void kernel_launch(void* const* d_in, const int* in_sizes, int n_in,
                              void* d_out, int out_size)
{
    const float* x  = (const float*)d_in[0];
    const float* Wq = (const float*)d_in[1];
    const float* bq = (const float*)d_in[2];
    const float* Wk = (const float*)d_in[3];
    const float* bk = (const float*)d_in[4];
    const float* Wv = (const float*)d_in[5];
    const float* bv = (const float*)d_in[6];
    const float* Wo = (const float*)d_in[7];
    const float* bo = (const float*)d_in[8];
    float* out = (float*)d_out;

    float *qp, *kp, *aop;
    __nv_bfloat16* vtp;
    cudaGetSymbolAddress((void**)&qp,  g_q);
    cudaGetSymbolAddress((void**)&kp,  g_k);
    cudaGetSymbolAddress((void**)&vtp, g_vt);
    cudaGetSymbolAddress((void**)&aop, g_ao);

    cudaFuncSetAttribute(gemm_tc,
                         cudaFuncAttributeMaxDynamicSharedMemorySize,
                         (int)GEMM_SMEM);
    cudaFuncSetAttribute(attn_tc,
                         cudaFuncAttributeMaxDynamicSharedMemorySize,
                         (int)ATTN_SMEM);

    dim3 gridP(NTOK / 128, DIM / 64);   // 64 x 8

    gemm_tc<<<gridP, 256, GEMM_SMEM>>>(x, Wq, bq, qp, 1);
    gemm_tc<<<gridP, 256, GEMM_SMEM>>>(x, Wk, bk, kp, 1);
    gemm_tc<<<gridP, 256, GEMM_SMEM>>>(x, Wv, bv, (float*)vtp, 2);

    dim3 gridA(SEQ / 128, HEADS, BATCH);  // 32 x 8 x 2
    attn_tc<<<gridA, 256, ATTN_SMEM>>>(qp, kp, vtp, aop);

    gemm_tc<<<gridP, 256, GEMM_SMEM>>>(aop, Wo, bo, out, 0);
}

// round 8
// speedup vs baseline: 1.4985x; 1.0738x over previous
#include <cuda_runtime.h>
#include <cuda_bf16.h>
#include <math.h>
#include <stdint.h>

#define DIM   512
#define HEADS 8
#define DQ    64
#define SEQ   4096
#define BATCH 2
#define NTOK  (BATCH * SEQ)   // 8192

// Scratch (allocation-free rule: __device__ globals)
__device__ float g_q [NTOK * DIM];
__device__ float g_k [NTOK * DIM];
__device__ __nv_bfloat16 g_vt[NTOK * DIM];   // V transposed bf16: [b*512+m][4096]
__device__ float g_ao[NTOK * DIM];
__device__ float g_xr[NTOK * DIM];           // X pre-rounded to tf32
__device__ float g_wr[4 * DIM * DIM];        // Wq,Wk,Wv,Wo pre-rounded to tf32

// ---------------------------------------------------------------------------
// helpers
// ---------------------------------------------------------------------------
__device__ __forceinline__ uint32_t f2tf32(float f) {
    uint32_t u; asm("cvt.rna.tf32.f32 %0, %1;" : "=r"(u) : "f"(f)); return u;
}
__device__ __forceinline__ float f2tf32f(float f) { return __uint_as_float(f2tf32(f)); }

__device__ __forceinline__ float ex2f(float x) {
    float y; asm("ex2.approx.ftz.f32 %0, %1;" : "=f"(y) : "f"(x)); return y;
}

__device__ __forceinline__ uint32_t pack_bf16(float lo, float hi) {
    uint32_t r; asm("cvt.rn.bf16x2.f32 %0, %1, %2;" : "=r"(r) : "f"(hi), "f"(lo));
    return r;
}

__device__ __forceinline__ void ldsm_x4(uint32_t r[4], const float* p) {
    uint32_t a = (uint32_t)__cvta_generic_to_shared(p);
    asm volatile("ldmatrix.sync.aligned.m8n8.x4.shared.b16 {%0,%1,%2,%3}, [%4];"
                 : "=r"(r[0]), "=r"(r[1]), "=r"(r[2]), "=r"(r[3])
                 : "r"(a) : "memory");
}
__device__ __forceinline__ void ldsm_x4b(uint32_t r[4], const __nv_bfloat16* p) {
    uint32_t a = (uint32_t)__cvta_generic_to_shared(p);
    asm volatile("ldmatrix.sync.aligned.m8n8.x4.shared.b16 {%0,%1,%2,%3}, [%4];"
                 : "=r"(r[0]), "=r"(r[1]), "=r"(r[2]), "=r"(r[3])
                 : "r"(a) : "memory");
}

__device__ __forceinline__ void mma_tf32(float c[4], const uint32_t a[4],
                                         uint32_t b0, uint32_t b1) {
    asm volatile("mma.sync.aligned.m16n8k8.row.col.f32.tf32.tf32.f32 "
                 "{%0,%1,%2,%3}, {%4,%5,%6,%7}, {%8,%9}, {%0,%1,%2,%3};"
                 : "+f"(c[0]), "+f"(c[1]), "+f"(c[2]), "+f"(c[3])
                 : "r"(a[0]), "r"(a[1]), "r"(a[2]), "r"(a[3]), "r"(b0), "r"(b1));
}

__device__ __forceinline__ void mma_bf16(float c[4], const uint32_t a[4],
                                         uint32_t b0, uint32_t b1) {
    asm volatile("mma.sync.aligned.m16n8k16.row.col.f32.bf16.bf16.f32 "
                 "{%0,%1,%2,%3}, {%4,%5,%6,%7}, {%8,%9}, {%0,%1,%2,%3};"
                 : "+f"(c[0]), "+f"(c[1]), "+f"(c[2]), "+f"(c[3])
                 : "r"(a[0]), "r"(a[1]), "r"(a[2]), "r"(a[3]), "r"(b0), "r"(b1));
}

__device__ __forceinline__ void cp16(float* smem_dst, const float* gsrc) {
    uint32_t a = (uint32_t)__cvta_generic_to_shared(smem_dst);
    asm volatile("cp.async.cg.shared.global [%0], [%1], 16;" :: "r"(a), "l"(gsrc));
}
__device__ __forceinline__ void cp16b(__nv_bfloat16* smem_dst, const __nv_bfloat16* gsrc) {
    uint32_t a = (uint32_t)__cvta_generic_to_shared(smem_dst);
    asm volatile("cp.async.cg.shared.global [%0], [%1], 16;" :: "r"(a), "l"(gsrc));
}
#define CP_COMMIT() asm volatile("cp.async.commit_group;")
#define CP_WAIT1()  asm volatile("cp.async.wait_group 1;")

// ---------------------------------------------------------------------------
// Pre-round fp32 -> tf32 bits (n divisible by 1024; 4 elems/thread)
// ---------------------------------------------------------------------------
__global__ __launch_bounds__(256) void round_tf32_kernel(
    const float* __restrict__ s, float* __restrict__ d)
{
    int i = (blockIdx.x * 256 + threadIdx.x) * 4;
    float4 v = *(const float4*)&s[i];
    float4 o;
    o.x = f2tf32f(v.x); o.y = f2tf32f(v.y);
    o.z = f2tf32f(v.z); o.w = f2tf32f(v.w);
    *(float4*)&d[i] = o;
}

// ---------------------------------------------------------------------------
// Tensor-core GEMM (operands PRE-ROUNDED tf32 -> no in-loop cvt).
// C[n,m] = sum_k X[n,k]*W[m,k] + bias[m]   (K = 512)
// CTA: 128 tokens x 64 cols.  8 warps.  cp.async double-buffered k-steps of 32.
// mode 0: plain fp32 out.  mode 1: tf32-rounded out (Q/K).
// mode 2: transposed bf16 out (V -> [b*512+m][4096]).
// ---------------------------------------------------------------------------
#define GP 36   // shared pitch (floats)
#define GEMM_SMEM ((2*128 + 2*64) * GP * sizeof(float))   // 55296 B

__global__ __launch_bounds__(256) void gemm_tc(
    const float* __restrict__ X, const float* __restrict__ W,
    const float* __restrict__ bias, float* __restrict__ C, int mode)
{
    extern __shared__ float sm[];
    float* Xs[2] = { sm, sm + 128 * GP };
    float* Ws[2] = { sm + 256 * GP, sm + 256 * GP + 64 * GP };

    const int tid = threadIdx.x;
    const int L   = tid & 31;
    const int wid = tid >> 5;
    const int n0  = blockIdx.x * 128;
    const int m0  = blockIdx.y * 64;

    float c[8][4] = {};

    const int arow = wid * 16 + ((L >> 3) & 1) * 8 + (L & 7);
    const int acol = (L >> 4) * 4;
    const int brow = (L >> 4) * 8 + (L & 7);
    const int bcol = ((L >> 3) & 1) * 4;

    const int xrow = tid >> 3, xc4 = (tid & 7) * 4;
    #pragma unroll
    for (int r = 0; r < 4; r++)
        cp16(&Xs[0][(xrow + 32 * r) * GP + xc4],
             &X[(size_t)(n0 + xrow + 32 * r) * DIM + xc4]);
    #pragma unroll
    for (int r = 0; r < 2; r++)
        cp16(&Ws[0][(xrow + 32 * r) * GP + xc4],
             &W[(size_t)(m0 + xrow + 32 * r) * DIM + xc4]);
    CP_COMMIT();

    const int NK = DIM / 32;   // 16
    for (int t = 0; t < NK; t++) {
        int nb = (t + 1) & 1;
        if (t + 1 < NK) {
            int k0 = (t + 1) * 32;
            #pragma unroll
            for (int r = 0; r < 4; r++)
                cp16(&Xs[nb][(xrow + 32 * r) * GP + xc4],
                     &X[(size_t)(n0 + xrow + 32 * r) * DIM + k0 + xc4]);
            #pragma unroll
            for (int r = 0; r < 2; r++)
                cp16(&Ws[nb][(xrow + 32 * r) * GP + xc4],
                     &W[(size_t)(m0 + xrow + 32 * r) * DIM + k0 + xc4]);
        }
        CP_COMMIT();
        CP_WAIT1();
        __syncthreads();

        const float* Xb = Xs[t & 1];
        const float* Wb = Ws[t & 1];
        #pragma unroll
        for (int ks = 0; ks < 4; ks++) {
            uint32_t a[4];
            ldsm_x4(a, &Xb[arow * GP + ks * 8 + acol]);
            #pragma unroll
            for (int jp = 0; jp < 4; jp++) {
                uint32_t b[4];
                ldsm_x4(b, &Wb[(jp * 16 + brow) * GP + ks * 8 + bcol]);
                mma_tf32(c[jp * 2 + 0], a, b[0], b[1]);
                mma_tf32(c[jp * 2 + 1], a, b[2], b[3]);
            }
        }
        __syncthreads();
    }

    const int rlo  = n0 + wid * 16 + (L >> 2);
    const int colb = 2 * (L & 3);
    if (mode == 0) {
        #pragma unroll
        for (int j = 0; j < 8; j++) {
            int col = m0 + j * 8 + colb;
            float b0 = bias[col], b1 = bias[col + 1];
            *(float2*)&C[(size_t)rlo * DIM + col] =
                make_float2(c[j][0] + b0, c[j][1] + b1);
            *(float2*)&C[(size_t)(rlo + 8) * DIM + col] =
                make_float2(c[j][2] + b0, c[j][3] + b1);
        }
    } else if (mode == 1) {
        #pragma unroll
        for (int j = 0; j < 8; j++) {
            int col = m0 + j * 8 + colb;
            float b0 = bias[col], b1 = bias[col + 1];
            *(float2*)&C[(size_t)rlo * DIM + col] =
                make_float2(f2tf32f(c[j][0] + b0), f2tf32f(c[j][1] + b1));
            *(float2*)&C[(size_t)(rlo + 8) * DIM + col] =
                make_float2(f2tf32f(c[j][2] + b0), f2tf32f(c[j][3] + b1));
        }
    } else {
        __nv_bfloat16* Cb = (__nv_bfloat16*)C;
        int b_lo = rlo >> 12, t_lo = rlo & 4095;
        int rhi = rlo + 8;
        int b_hi = rhi >> 12, t_hi = rhi & 4095;
        #pragma unroll
        for (int j = 0; j < 8; j++) {
            int m = m0 + j * 8 + colb;
            float bb0 = bias[m], bb1 = bias[m + 1];
            Cb[(size_t)(b_lo * DIM + m)     * SEQ + t_lo] = __float2bfloat16(c[j][0] + bb0);
            Cb[(size_t)(b_lo * DIM + m + 1) * SEQ + t_lo] = __float2bfloat16(c[j][1] + bb1);
            Cb[(size_t)(b_hi * DIM + m)     * SEQ + t_hi] = __float2bfloat16(c[j][2] + bb0);
            Cb[(size_t)(b_hi * DIM + m + 1) * SEQ + t_hi] = __float2bfloat16(c[j][3] + bb1);
        }
    }
}

// ---------------------------------------------------------------------------
// Flash attention: QK tf32, PV bf16, register-resident P.
// log2e folded into Q scale -> raw ex2 softmax; lane-partial l (no per-tile
// sum shuffles).  Grid (SEQ/128, HEADS, BATCH); 256 threads (8 warps).
// ---------------------------------------------------------------------------
#define AP  68   // fp32 shared pitch (Q/K)
#define VPB 72   // bf16 shared pitch (V)
#define ATTN_SMEM (256 * AP * 4 + 2 * 64 * VPB * 2)   // 88064 B

__global__ __launch_bounds__(256, 2) void attn_tc(
    const float* __restrict__ Q, const float* __restrict__ K,
    const __nv_bfloat16* __restrict__ Vt, float* __restrict__ O)
{
    extern __shared__ float sm[];
    float* Qsm = sm;                                    // 128 x AP
    float* Ksm[2] = { sm + 128 * AP, sm + 192 * AP };   // 64 x AP each
    __nv_bfloat16* Vbase = (__nv_bfloat16*)(sm + 256 * AP);
    __nv_bfloat16* Vsm[2] = { Vbase, Vbase + 64 * VPB };  // 64(dq) x VPB(keys)

    const int tid = threadIdx.x;
    const int L   = tid & 31;
    const int wid = tid >> 5;
    const int q0  = blockIdx.x * 128;
    const int h   = blockIdx.y;
    const int b   = blockIdx.z;
    const size_t qk_base = (size_t)b * SEQ * DIM + (size_t)h * DQ;
    const size_t vt_base = (size_t)(b * DIM + h * DQ) * SEQ;

    const int lrow = tid >> 4, lc4 = (tid & 15) * 4;
    const int vrow = tid >> 2, vc8 = (tid & 3) * 8;

    // prologue: cp.async K/V tile 0
    #pragma unroll
    for (int r = 0; r < 4; r++) {
        int row = lrow + 16 * r;
        cp16(&Ksm[0][row * AP + lc4], &K[qk_base + (size_t)row * DIM + lc4]);
    }
    cp16b(&Vsm[0][vrow * VPB + vc8],      &Vt[vt_base + (size_t)vrow * SEQ + vc8]);
    cp16b(&Vsm[0][vrow * VPB + vc8 + 32], &Vt[vt_base + (size_t)vrow * SEQ + vc8 + 32]);
    CP_COMMIT();

    // Load Q tile, scale by (1/8)*log2(e), re-round to tf32
    const float QSCALE = 0.125f * 1.44269504088896f;
    #pragma unroll
    for (int r = 0; r < 8; r++) {
        int e = tid + 256 * r;
        int row = e >> 4, c4 = (e & 15) * 4;
        float4 v = *(const float4*)&Q[qk_base + (size_t)(q0 + row) * DIM + c4];
        Qsm[row * AP + c4 + 0] = f2tf32f(v.x * QSCALE);
        Qsm[row * AP + c4 + 1] = f2tf32f(v.y * QSCALE);
        Qsm[row * AP + c4 + 2] = f2tf32f(v.z * QSCALE);
        Qsm[row * AP + c4 + 3] = f2tf32f(v.w * QSCALE);
    }
    __syncthreads();

    const int arow = wid * 16 + ((L >> 3) & 1) * 8 + (L & 7);
    const int acol = (L >> 4) * 4;
    const int brow = (L >> 4) * 8 + (L & 7);
    const int bcol = ((L >> 3) & 1) * 4;
    const int vlrow = L & 7;
    const int vlcol = ((L >> 3) & 1) * 8 + ((L >> 4) & 1) * 16;

    uint32_t qf[8][4];
    #pragma unroll
    for (int ks = 0; ks < 8; ks++)
        ldsm_x4(qf[ks], &Qsm[arow * AP + ks * 8 + acol]);

    float m_lo = -1e30f, m_hi = -1e30f;
    float l_lo = 0.f, l_hi = 0.f;          // LANE-PARTIAL (reduced at end)
    float o[8][4] = {};

    const int NT = SEQ / 64;
    for (int t = 0; t < NT; t++) {
        if (t + 1 < NT) {
            int nb = (t + 1) & 1;
            int k0 = (t + 1) * 64;
            #pragma unroll
            for (int r = 0; r < 4; r++) {
                int row = lrow + 16 * r;
                cp16(&Ksm[nb][row * AP + lc4],
                     &K[qk_base + (size_t)(k0 + row) * DIM + lc4]);
            }
            cp16b(&Vsm[nb][vrow * VPB + vc8],
                  &Vt[vt_base + (size_t)vrow * SEQ + k0 + vc8]);
            cp16b(&Vsm[nb][vrow * VPB + vc8 + 32],
                  &Vt[vt_base + (size_t)vrow * SEQ + k0 + vc8 + 32]);
        }
        CP_COMMIT();
        CP_WAIT1();
        __syncthreads();

        const float* Kb = Ksm[t & 1];
        const __nv_bfloat16* Vb = Vsm[t & 1];

        // S = Q @ K^T  (logits already in log2 domain)
        float s[8][4] = {};
        #pragma unroll
        for (int ks = 0; ks < 8; ks++) {
            #pragma unroll
            for (int jp = 0; jp < 4; jp++) {
                uint32_t bf[4];
                ldsm_x4(bf, &Kb[(jp * 16 + brow) * AP + ks * 8 + bcol]);
                mma_tf32(s[jp * 2 + 0], qf[ks], bf[0], bf[1]);
                mma_tf32(s[jp * 2 + 1], qf[ks], bf[2], bf[3]);
            }
        }

        // Online softmax (base-2).  Max reduce across quad; sums stay lane-local.
        float mx_lo = -1e30f, mx_hi = -1e30f;
        #pragma unroll
        for (int j = 0; j < 8; j++) {
            mx_lo = fmaxf(mx_lo, fmaxf(s[j][0], s[j][1]));
            mx_hi = fmaxf(mx_hi, fmaxf(s[j][2], s[j][3]));
        }
        mx_lo = fmaxf(mx_lo, __shfl_xor_sync(0xffffffffu, mx_lo, 1));
        mx_lo = fmaxf(mx_lo, __shfl_xor_sync(0xffffffffu, mx_lo, 2));
        mx_hi = fmaxf(mx_hi, __shfl_xor_sync(0xffffffffu, mx_hi, 1));
        mx_hi = fmaxf(mx_hi, __shfl_xor_sync(0xffffffffu, mx_hi, 2));

        float mn_lo = fmaxf(m_lo, mx_lo), mn_hi = fmaxf(m_hi, mx_hi);
        float al = ex2f(m_lo - mn_lo),  ah = ex2f(m_hi - mn_hi);
        m_lo = mn_lo; m_hi = mn_hi;

        float sum_lo = 0.f, sum_hi = 0.f;
        #pragma unroll
        for (int j = 0; j < 8; j++) {
            s[j][0] = ex2f(s[j][0] - mn_lo);
            s[j][1] = ex2f(s[j][1] - mn_lo);
            s[j][2] = ex2f(s[j][2] - mn_hi);
            s[j][3] = ex2f(s[j][3] - mn_hi);
            sum_lo += s[j][0] + s[j][1];
            sum_hi += s[j][2] + s[j][3];
        }
        l_lo = l_lo * al + sum_lo;
        l_hi = l_hi * ah + sum_hi;

        #pragma unroll
        for (int j = 0; j < 8; j++) {
            o[j][0] *= al; o[j][1] *= al;
            o[j][2] *= ah; o[j][3] *= ah;
        }

        // Pack P into bf16 A-fragments in registers
        uint32_t p[16];
        #pragma unroll
        for (int kb = 0; kb < 4; kb++) {
            p[kb * 4 + 0] = pack_bf16(s[2 * kb][0],     s[2 * kb][1]);
            p[kb * 4 + 1] = pack_bf16(s[2 * kb][2],     s[2 * kb][3]);
            p[kb * 4 + 2] = pack_bf16(s[2 * kb + 1][0], s[2 * kb + 1][1]);
            p[kb * 4 + 3] = pack_bf16(s[2 * kb + 1][2], s[2 * kb + 1][3]);
        }

        // O += P @ V
        #pragma unroll
        for (int m2 = 0; m2 < 2; m2++) {
            #pragma unroll
            for (int jp = 0; jp < 8; jp++) {
                uint32_t bf[4];
                ldsm_x4b(bf, &Vb[(jp * 8 + vlrow) * VPB + m2 * 32 + vlcol]);
                mma_bf16(o[jp], &p[(2 * m2) * 4],     bf[0], bf[1]);
                mma_bf16(o[jp], &p[(2 * m2 + 1) * 4], bf[2], bf[3]);
            }
        }
        __syncthreads();
    }

    // Epilogue: reduce lane-partial l across quad, normalize, write tf32 bits
    l_lo += __shfl_xor_sync(0xffffffffu, l_lo, 1);
    l_lo += __shfl_xor_sync(0xffffffffu, l_lo, 2);
    l_hi += __shfl_xor_sync(0xffffffffu, l_hi, 1);
    l_hi += __shfl_xor_sync(0xffffffffu, l_hi, 2);
    float il = 1.f / l_lo, ih = 1.f / l_hi;
    const int row = q0 + wid * 16 + (L >> 2);
    #pragma unroll
    for (int j = 0; j < 8; j++) {
        int col = j * 8 + 2 * (L & 3);
        *(float2*)&O[qk_base + (size_t)row * DIM + col] =
            make_float2(f2tf32f(o[j][0] * il), f2tf32f(o[j][1] * il));
        *(float2*)&O[qk_base + (size_t)(row + 8) * DIM + col] =
            make_float2(f2tf32f(o[j][2] * ih), f2tf32f(o[j][3] * ih));
    }
}

// ---------------------------------------------------------------------------
extern "C" void kernel_launch(void* const* d_in, const int* in_sizes, int n_in,
                              void* d_out, int out_size)
{
    const float* x  = (const float*)d_in[0];
    const float* Wq = (const float*)d_in[1];
    const float* bq = (const float*)d_in[2];
    const float* Wk = (const float*)d_in[3];
    const float* bk = (const float*)d_in[4];
    const float* Wv = (const float*)d_in[5];
    const float* bv = (const float*)d_in[6];
    const float* Wo = (const float*)d_in[7];
    const float* bo = (const float*)d_in[8];
    float* out = (float*)d_out;

    float *qp, *kp, *aop, *xrp, *wrp;
    __nv_bfloat16* vtp;
    cudaGetSymbolAddress((void**)&qp,  g_q);
    cudaGetSymbolAddress((void**)&kp,  g_k);
    cudaGetSymbolAddress((void**)&vtp, g_vt);
    cudaGetSymbolAddress((void**)&aop, g_ao);
    cudaGetSymbolAddress((void**)&xrp, g_xr);
    cudaGetSymbolAddress((void**)&wrp, g_wr);

    cudaFuncSetAttribute(gemm_tc,
                         cudaFuncAttributeMaxDynamicSharedMemorySize,
                         (int)GEMM_SMEM);
    cudaFuncSetAttribute(attn_tc,
                         cudaFuncAttributeMaxDynamicSharedMemorySize,
                         (int)ATTN_SMEM);

    // Pre-round X and weights to tf32 (removes all in-loop cvt from GEMMs)
    const int WSZ = DIM * DIM;              // 262144
    round_tf32_kernel<<<NTOK * DIM / 1024, 256>>>(x,  xrp);
    round_tf32_kernel<<<WSZ / 1024, 256>>>(Wq, wrp + 0 * WSZ);
    round_tf32_kernel<<<WSZ / 1024, 256>>>(Wk, wrp + 1 * WSZ);
    round_tf32_kernel<<<WSZ / 1024, 256>>>(Wv, wrp + 2 * WSZ);
    round_tf32_kernel<<<WSZ / 1024, 256>>>(Wo, wrp + 3 * WSZ);

    dim3 gridP(NTOK / 128, DIM / 64);   // 64 x 8

    gemm_tc<<<gridP, 256, GEMM_SMEM>>>(xrp, wrp + 0 * WSZ, bq, qp, 1);
    gemm_tc<<<gridP, 256, GEMM_SMEM>>>(xrp, wrp + 1 * WSZ, bk, kp, 1);
    gemm_tc<<<gridP, 256, GEMM_SMEM>>>(xrp, wrp + 2 * WSZ, bv, (float*)vtp, 2);

    dim3 gridA(SEQ / 128, HEADS, BATCH);  // 32 x 8 x 2
    attn_tc<<<gridA, 256, ATTN_SMEM>>>(qp, kp, vtp, aop);

    gemm_tc<<<gridP, 256, GEMM_SMEM>>>(aop, wrp + 3 * WSZ, bo, out, 0);
}